// round 7
// baseline (speedup 1.0000x reference)
#include <cuda_runtime.h>
#include <cuda_bf16.h>

// DimMasking R6: incremental multiplicative softmax (packed f32x2).
//  - 5-SHFL butterfly reduce (redux.f32 does NOT exist on sm_103)
//  - GEMM broadcast operands loaded as float4 (4x fewer LDS/MIO ops)
//  - slow-path trigger on float min (fma pipe), no integer ISETPs
//  - lane-sum fused into update loop, two accumulator trees

#define DD       640
#define HID      64
#define N_ITER   64
#define INV_T    (1.0f / 0.07f)
#define LOG2E    1.4426950408889634f
#define RPC      8
#define NP       10              // pairs per lane (640/32/2)
#define YT       0.02f

typedef unsigned long long u64;

__device__ __forceinline__ u64 fma2(u64 a, u64 b, u64 c) {
    u64 d; asm("fma.rn.f32x2 %0, %1, %2, %3;" : "=l"(d) : "l"(a), "l"(b), "l"(c)); return d;
}
__device__ __forceinline__ u64 mul2(u64 a, u64 b) {
    u64 d; asm("mul.rn.f32x2 %0, %1, %2;" : "=l"(d) : "l"(a), "l"(b)); return d;
}
__device__ __forceinline__ u64 add2(u64 a, u64 b) {
    u64 d; asm("add.rn.f32x2 %0, %1, %2;" : "=l"(d) : "l"(a), "l"(b)); return d;
}
__device__ __forceinline__ u64 pack2(float x, float y) {
    u64 r; asm("mov.b64 %0, {%1, %2};" : "=l"(r) : "f"(x), "f"(y)); return r;
}
__device__ __forceinline__ float2 unpack2(u64 v) {
    float2 f; asm("mov.b64 {%0, %1}, %2;" : "=f"(f.x), "=f"(f.y) : "l"(v)); return f;
}
__device__ __forceinline__ float ex2f(float x) {
    float r; asm("ex2.approx.ftz.f32 %0, %1;" : "=f"(r) : "f"(x)); return r;
}
__device__ __forceinline__ float lg2f(float x) {
    float r; asm("lg2.approx.ftz.f32 %0, %1;" : "=f"(r) : "f"(x)); return r;
}
__device__ __forceinline__ float rcpf(float x) {
    float r; asm("rcp.approx.ftz.f32 %0, %1;" : "=f"(r) : "f"(x)); return r;
}
__device__ __forceinline__ float warp_sum(float v) {
    #pragma unroll
    for (int o = 16; o > 0; o >>= 1)
        v += __shfl_xor_sync(0xffffffffu, v, o);
    return v;
}
__device__ __forceinline__ float warp_max(float v) {
    #pragma unroll
    for (int o = 16; o > 0; o >>= 1)
        v = fmaxf(v, __shfl_xor_sync(0xffffffffu, v, o));
    return v;
}

__global__ __launch_bounds__(RPC * 32, 5)
void dim_masking_kernel(const float* __restrict__ x,
                        const float* __restrict__ W1,
                        const float* __restrict__ b1,
                        const float* __restrict__ W2,
                        const float* __restrict__ b2,
                        float* __restrict__ out)
{
    __shared__ __align__(16) float xs[RPC][DD];
    __shared__ __align__(16) float hs[RPC][HID];

    const int w    = threadIdx.x >> 5;
    const int lane = threadIdx.x & 31;
    const int row  = blockIdx.x * RPC + w;

    const u64* xr = (const u64*)(x + (size_t)row * DD);

    // ---- stage x row into smem (coalesced 64-bit) ----
    #pragma unroll
    for (int j = 0; j < NP; j++)
        *(u64*)&xs[w][2 * (lane + 32 * j)] = xr[lane + 32 * j];
    __syncwarp();

    // ---- GEMM1: hidden units (2*lane, 2*lane+1); x broadcast as float4 ----
    const float4* xs4 = (const float4*)xs[w];
    u64 acc1 = *(const u64*)&b1[2 * lane];
    #pragma unroll 4
    for (int d4 = 0; d4 < DD / 4; d4++) {
        float4 xv = xs4[d4];
        const u64* w1r = (const u64*)&W1[(4 * d4) * HID + 2 * lane];
        acc1 = fma2(pack2(xv.x, xv.x), w1r[0 * HID / 2], acc1);
        acc1 = fma2(pack2(xv.y, xv.y), w1r[1 * HID / 2], acc1);
        acc1 = fma2(pack2(xv.z, xv.z), w1r[2 * HID / 2], acc1);
        acc1 = fma2(pack2(xv.w, xv.w), w1r[3 * HID / 2], acc1);
    }
    {
        float2 a = unpack2(acc1);
        hs[w][2 * lane]     = fmaxf(a.x, 0.0f);
        hs[w][2 * lane + 1] = fmaxf(a.y, 0.0f);
    }
    __syncwarp();

    // ---- GEMM2: h pairs at dims 2*lane + 64*j; hidden broadcast as float4 ----
    const float4* hs4 = (const float4*)hs[w];
    u64 h2[NP];
    #pragma unroll
    for (int j = 0; j < NP; j++)
        h2[j] = *(const u64*)&b2[2 * lane + 64 * j];
    #pragma unroll 2
    for (int c4 = 0; c4 < HID / 4; c4++) {
        float4 hv = hs4[c4];
        #pragma unroll
        for (int i = 0; i < 4; i++) {
            float hc = (i == 0) ? hv.x : (i == 1) ? hv.y : (i == 2) ? hv.z : hv.w;
            u64 hvv = pack2(hc, hc);
            const float* w2r = &W2[(4 * c4 + i) * DD + 2 * lane];
            #pragma unroll
            for (int j = 0; j < NP; j++)
                h2[j] = fma2(hvv, *(const u64*)&w2r[64 * j], h2[j]);
        }
    }

    // ---- init: p = exp2(l - max l); m = 1; running packed sum ----
    float lx[NP], ly[NP];
    float M0 = -3.402823e38f;
    #pragma unroll
    for (int j = 0; j < NP; j++) {
        float2 hf = unpack2(h2[j]);
        lx[j] = -hf.x * (INV_T * LOG2E);
        ly[j] = -hf.y * (INV_T * LOG2E);
        M0 = fmaxf(M0, fmaxf(lx[j], ly[j]));
    }
    M0 = warp_max(M0);

    u64 p[NP], m[NP];
    const u64 ONE2 = pack2(1.0f, 1.0f);
    u64 sacc = 0;
    #pragma unroll
    for (int j = 0; j < NP; j++) {
        p[j] = pack2(ex2f(lx[j] - M0), ex2f(ly[j] - M0));
        m[j] = ONE2;
        sacc = (j == 0) ? p[0] : add2(sacc, p[j]);
    }

    const u64 K1 = pack2(14.285714285714286f, 14.285714285714286f);
    const u64 K2 = pack2(94.89795918367347f,  94.89795918367347f);
    const u64 K3 = pack2(388.6297376093295f,  388.6297376093295f);
    const u64 K4 = pack2(1096.491194f,        1096.491194f);

    // ---- 64-iteration incremental recurrence ----
    #pragma unroll 1
    for (int it = 0; it < N_ITER; it++) {
        float2 sf = unpack2(sacc);
        float S = warp_sum(sf.x + sf.y);
        float nrS = -rcpf(S);
        u64 nrS2 = pack2(nrS, nrS);

        u64 sn0 = 0, sn1 = 0;
        #pragma unroll
        for (int j = 0; j < NP; j++) {
            u64 z = mul2(p[j], nrS2);            // z = -y, y = p/S
            u64 t = fma2(z, K4, K3);
            t = fma2(z, t, K2);
            t = fma2(z, t, K1);
            u64 f = fma2(z, t, ONE2);            // (1+z)^{1/T} poly, |z|<=0.02
            float2 zf = unpack2(z);              // reg-aliased halves
            if (fminf(zf.x, zf.y) < -YT) {       // rare exact path
                float2 ff = unpack2(f);
                if (zf.x < -YT)
                    ff.x = ex2f(lg2f(fmaxf(1.0f + zf.x, 0.0f)) * INV_T);
                if (zf.y < -YT)
                    ff.y = ex2f(lg2f(fmaxf(1.0f + zf.y, 0.0f)) * INV_T);
                f = pack2(ff.x, ff.y);
            }
            p[j] = mul2(p[j], f);
            m[j] = fma2(z, m[j], m[j]);          // m *= (1 - y)
            if (j & 1) sn1 = (j == 1) ? p[1] : add2(sn1, p[j]);
            else       sn0 = (j == 0) ? p[0] : add2(sn0, p[j]);
        }
        sacc = add2(sn0, sn1);
    }

    // ---- out = m * x ----
    u64* orow = (u64*)(out + (size_t)row * DD);
    #pragma unroll
    for (int j = 0; j < NP; j++) {
        u64 xv = *(const u64*)&xs[w][2 * (lane + 32 * j)];
        orow[lane + 32 * j] = mul2(m[j], xv);
    }
}

extern "C" void kernel_launch(void* const* d_in, const int* in_sizes, int n_in,
                              void* d_out, int out_size)
{
    const float* x  = (const float*)d_in[0];   // (8192, 640)
    const float* W1 = (const float*)d_in[1];   // (640, 64)
    const float* b1 = (const float*)d_in[2];   // (64,)
    const float* W2 = (const float*)d_in[3];   // (64, 640)
    const float* b2 = (const float*)d_in[4];   // (640,)
    float* out = (float*)d_out;

    const int B = in_sizes[0] / DD;            // 8192
    dim_masking_kernel<<<B / RPC, RPC * 32>>>(x, W1, b1, W2, b2, out);
}

// round 8
// speedup vs baseline: 1.0319x; 1.0319x over previous
#include <cuda_runtime.h>
#include <cuda_bf16.h>

// DimMasking R7: two rows per warp. The per-iteration serial chain
// (sum -> 5xSHFL -> rcp -> broadcast) of row A overlaps with row B's
// update-loop instructions and vice versa; shared W1/W2 loads serve both rows.
//  - packed f32x2 (FFMA2) math, degree-4 poly for (1-y)^{1/T}, MUFU fallback
//  - 128-thread CTAs (4 warps x 2 rows = 8 rows/CTA), launch_bounds(128,4)

#define DD       640
#define HID      64
#define N_ITER   64
#define INV_T    (1.0f / 0.07f)
#define LOG2E    1.4426950408889634f
#define RPC      8               // rows per CTA
#define NP       10              // pairs per lane per row (640/32/2)
#define YT       0.02f

typedef unsigned long long u64;

__device__ __forceinline__ u64 fma2(u64 a, u64 b, u64 c) {
    u64 d; asm("fma.rn.f32x2 %0, %1, %2, %3;" : "=l"(d) : "l"(a), "l"(b), "l"(c)); return d;
}
__device__ __forceinline__ u64 mul2(u64 a, u64 b) {
    u64 d; asm("mul.rn.f32x2 %0, %1, %2;" : "=l"(d) : "l"(a), "l"(b)); return d;
}
__device__ __forceinline__ u64 add2(u64 a, u64 b) {
    u64 d; asm("add.rn.f32x2 %0, %1, %2;" : "=l"(d) : "l"(a), "l"(b)); return d;
}
__device__ __forceinline__ u64 pack2(float x, float y) {
    u64 r; asm("mov.b64 %0, {%1, %2};" : "=l"(r) : "f"(x), "f"(y)); return r;
}
__device__ __forceinline__ float2 unpack2(u64 v) {
    float2 f; asm("mov.b64 {%0, %1}, %2;" : "=f"(f.x), "=f"(f.y) : "l"(v)); return f;
}
__device__ __forceinline__ float ex2f(float x) {
    float r; asm("ex2.approx.ftz.f32 %0, %1;" : "=f"(r) : "f"(x)); return r;
}
__device__ __forceinline__ float lg2f(float x) {
    float r; asm("lg2.approx.ftz.f32 %0, %1;" : "=f"(r) : "f"(x)); return r;
}
__device__ __forceinline__ float rcpf(float x) {
    float r; asm("rcp.approx.ftz.f32 %0, %1;" : "=f"(r) : "f"(x)); return r;
}

__global__ __launch_bounds__(128, 4)
void dim_masking_kernel(const float* __restrict__ x,
                        const float* __restrict__ W1,
                        const float* __restrict__ b1,
                        const float* __restrict__ W2,
                        const float* __restrict__ b2,
                        float* __restrict__ out)
{
    __shared__ __align__(16) float xs[RPC][DD];
    __shared__ __align__(16) float hs[RPC][HID];

    const int w    = threadIdx.x >> 5;     // 0..3
    const int lane = threadIdx.x & 31;
    const int ra   = 2 * w;                // local rows
    const int rb   = 2 * w + 1;
    const int rowa = blockIdx.x * RPC + ra;

    const u64* xra = (const u64*)(x + (size_t)rowa * DD);
    const u64* xrb = (const u64*)(x + (size_t)(rowa + 1) * DD);

    // ---- stage both rows into smem ----
    #pragma unroll
    for (int j = 0; j < NP; j++) {
        *(u64*)&xs[ra][2 * (lane + 32 * j)] = xra[lane + 32 * j];
        *(u64*)&xs[rb][2 * (lane + 32 * j)] = xrb[lane + 32 * j];
    }
    __syncwarp();

    // ---- GEMM1: one W1 load feeds both rows ----
    const float4* xsa4 = (const float4*)xs[ra];
    const float4* xsb4 = (const float4*)xs[rb];
    u64 acca = *(const u64*)&b1[2 * lane];
    u64 accb = acca;
    #pragma unroll 2
    for (int d4 = 0; d4 < DD / 4; d4++) {
        float4 xa = xsa4[d4];
        float4 xb = xsb4[d4];
        const u64* w1r = (const u64*)&W1[(4 * d4) * HID + 2 * lane];
        u64 wv0 = w1r[0 * HID / 2];
        u64 wv1 = w1r[1 * HID / 2];
        u64 wv2 = w1r[2 * HID / 2];
        u64 wv3 = w1r[3 * HID / 2];
        acca = fma2(pack2(xa.x, xa.x), wv0, acca);
        accb = fma2(pack2(xb.x, xb.x), wv0, accb);
        acca = fma2(pack2(xa.y, xa.y), wv1, acca);
        accb = fma2(pack2(xb.y, xb.y), wv1, accb);
        acca = fma2(pack2(xa.z, xa.z), wv2, acca);
        accb = fma2(pack2(xb.z, xb.z), wv2, accb);
        acca = fma2(pack2(xa.w, xa.w), wv3, acca);
        accb = fma2(pack2(xb.w, xb.w), wv3, accb);
    }
    {
        float2 a = unpack2(acca);
        float2 b = unpack2(accb);
        hs[ra][2 * lane]     = fmaxf(a.x, 0.0f);
        hs[ra][2 * lane + 1] = fmaxf(a.y, 0.0f);
        hs[rb][2 * lane]     = fmaxf(b.x, 0.0f);
        hs[rb][2 * lane + 1] = fmaxf(b.y, 0.0f);
    }
    __syncwarp();

    // ---- GEMM2: one W2 load feeds both rows ----
    u64 ha[NP], hb[NP];
    #pragma unroll
    for (int j = 0; j < NP; j++) {
        u64 bv = *(const u64*)&b2[2 * lane + 64 * j];
        ha[j] = bv;
        hb[j] = bv;
    }
    const float* hsa = hs[ra];
    const float* hsb = hs[rb];
    #pragma unroll 1
    for (int c = 0; c < HID; c++) {
        float hca = hsa[c];
        float hcb = hsb[c];
        u64 hva = pack2(hca, hca);
        u64 hvb = pack2(hcb, hcb);
        const float* w2r = &W2[c * DD + 2 * lane];
        #pragma unroll
        for (int j = 0; j < NP; j++) {
            u64 wv = *(const u64*)&w2r[64 * j];
            ha[j] = fma2(hva, wv, ha[j]);
            hb[j] = fma2(hvb, wv, hb[j]);
        }
    }

    // ---- init: logits in log2-domain; per-row max; p, m, sums ----
    const u64 NLT2 = pack2(-(INV_T * LOG2E), -(INV_T * LOG2E));
    float Ma = -3.402823e38f, Mb = Ma;
    #pragma unroll
    for (int j = 0; j < NP; j++) {
        ha[j] = mul2(ha[j], NLT2);
        hb[j] = mul2(hb[j], NLT2);
        float2 fa = unpack2(ha[j]);
        float2 fb = unpack2(hb[j]);
        Ma = fmaxf(Ma, fmaxf(fa.x, fa.y));
        Mb = fmaxf(Mb, fmaxf(fb.x, fb.y));
    }
    #pragma unroll
    for (int o = 16; o > 0; o >>= 1) {
        Ma = fmaxf(Ma, __shfl_xor_sync(0xffffffffu, Ma, o));
        Mb = fmaxf(Mb, __shfl_xor_sync(0xffffffffu, Mb, o));
    }

    u64 pa[NP], ma[NP], pb[NP], mb[NP];
    const u64 ONE2 = pack2(1.0f, 1.0f);
    u64 sacca = 0, saccb = 0;
    #pragma unroll
    for (int j = 0; j < NP; j++) {
        float2 fa = unpack2(ha[j]);
        float2 fb = unpack2(hb[j]);
        pa[j] = pack2(ex2f(fa.x - Ma), ex2f(fa.y - Ma));
        pb[j] = pack2(ex2f(fb.x - Mb), ex2f(fb.y - Mb));
        ma[j] = ONE2;
        mb[j] = ONE2;
        sacca = (j == 0) ? pa[0] : add2(sacca, pa[j]);
        saccb = (j == 0) ? pb[0] : add2(saccb, pb[j]);
    }

    const u64 K1 = pack2(14.285714285714286f, 14.285714285714286f);
    const u64 K2 = pack2(94.89795918367347f,  94.89795918367347f);
    const u64 K3 = pack2(388.6297376093295f,  388.6297376093295f);
    const u64 K4 = pack2(1096.491194f,        1096.491194f);

    // ---- 64-iteration recurrence, two rows interleaved ----
    #pragma unroll 1
    for (int it = 0; it < N_ITER; it++) {
        float2 sfa = unpack2(sacca);
        float2 sfb = unpack2(saccb);
        float Sa = sfa.x + sfa.y;
        float Sb = sfb.x + sfb.y;
        #pragma unroll
        for (int o = 16; o > 0; o >>= 1) {
            Sa += __shfl_xor_sync(0xffffffffu, Sa, o);
            Sb += __shfl_xor_sync(0xffffffffu, Sb, o);
        }
        u64 nrA = pack2(-rcpf(Sa), -rcpf(Sa));
        u64 nrB = pack2(-rcpf(Sb), -rcpf(Sb));

        u64 snA = 0, snB = 0;
        #pragma unroll
        for (int j = 0; j < NP; j++) {
            // row A pair j
            u64 za = mul2(pa[j], nrA);
            u64 ta = fma2(za, K4, K3);
            // row B pair j (interleaved for ILP)
            u64 zb = mul2(pb[j], nrB);
            u64 tb = fma2(zb, K4, K3);
            ta = fma2(za, ta, K2);
            tb = fma2(zb, tb, K2);
            ta = fma2(za, ta, K1);
            tb = fma2(zb, tb, K1);
            u64 fa = fma2(za, ta, ONE2);
            u64 fb = fma2(zb, tb, ONE2);
            float2 zaf = unpack2(za);
            float2 zbf = unpack2(zb);
            if (fminf(zaf.x, zaf.y) < -YT) {
                float2 ff = unpack2(fa);
                if (zaf.x < -YT) ff.x = ex2f(lg2f(fmaxf(1.0f + zaf.x, 0.0f)) * INV_T);
                if (zaf.y < -YT) ff.y = ex2f(lg2f(fmaxf(1.0f + zaf.y, 0.0f)) * INV_T);
                fa = pack2(ff.x, ff.y);
            }
            if (fminf(zbf.x, zbf.y) < -YT) {
                float2 ff = unpack2(fb);
                if (zbf.x < -YT) ff.x = ex2f(lg2f(fmaxf(1.0f + zbf.x, 0.0f)) * INV_T);
                if (zbf.y < -YT) ff.y = ex2f(lg2f(fmaxf(1.0f + zbf.y, 0.0f)) * INV_T);
                fb = pack2(ff.x, ff.y);
            }
            pa[j] = mul2(pa[j], fa);
            pb[j] = mul2(pb[j], fb);
            ma[j] = fma2(za, ma[j], ma[j]);
            mb[j] = fma2(zb, mb[j], mb[j]);
            snA = (j == 0) ? pa[0] : add2(snA, pa[j]);
            snB = (j == 0) ? pb[0] : add2(snB, pb[j]);
        }
        sacca = snA;
        saccb = snB;
    }

    // ---- out = m * x for both rows ----
    u64* ora = (u64*)(out + (size_t)rowa * DD);
    u64* orb = (u64*)(out + (size_t)(rowa + 1) * DD);
    #pragma unroll
    for (int j = 0; j < NP; j++) {
        u64 xa = *(const u64*)&xs[ra][2 * (lane + 32 * j)];
        u64 xb = *(const u64*)&xs[rb][2 * (lane + 32 * j)];
        ora[lane + 32 * j] = mul2(ma[j], xa);
        orb[lane + 32 * j] = mul2(mb[j], xb);
    }
}

extern "C" void kernel_launch(void* const* d_in, const int* in_sizes, int n_in,
                              void* d_out, int out_size)
{
    const float* x  = (const float*)d_in[0];   // (8192, 640)
    const float* W1 = (const float*)d_in[1];   // (640, 64)
    const float* b1 = (const float*)d_in[2];   // (64,)
    const float* W2 = (const float*)d_in[3];   // (64, 640)
    const float* b2 = (const float*)d_in[4];   // (640,)
    float* out = (float*)d_out;

    const int B = in_sizes[0] / DD;            // 8192
    dim_masking_kernel<<<B / RPC, 128>>>(x, W1, b1, W2, b2, out);
}